// round 9
// baseline (speedup 1.0000x reference)
#include <cuda_runtime.h>
#include <cuda_bf16.h>

// Submanifold sparse conv, 2 layers, C=64, KV=27, N=200000, grid 128^3, B=2.
// Per-offset pair buckets -> gather-GEMM: thread = (pair, 32-out-ch half),
// weights broadcast from smem (1 wavefront/LDS), FFMA2 math, RED.v4 output.

#define N_VOX   200000
#define C_CH    64
#define KV_     27
#define DD      128
#define BATCH   2
#define GRID_CELLS (BATCH * DD * DD * DD)

#define CAP_NC     16384
#define CH_CENTER  1563                     // ceil(200000/128)
#define CH_NC      128
#define TOT_ROWS   (N_VOX + 26 * CAP_NC)
#define GEMM_BLOCKS (CH_CENTER + 26 * CH_NC)

__device__ int   g_grid[GRID_CELLS];
__device__ int   g_cnt[KV_];
__device__ int   g_pin[TOT_ROWS];
__device__ int   g_pout[TOT_ROWS];
__device__ float g_mid[(size_t)N_VOX * C_CH];

__host__ __device__ __forceinline__ int bucket_base(int k) {
    if (k == 13) return 0;
    int j = (k < 13) ? k : k - 1;
    return N_VOX + j * CAP_NC;
}

// ------------------ init: grid=-1, counters=0, zero mid and out -------------
__global__ void init_kernel(float* __restrict__ out) {
    int tid0 = blockIdx.x * blockDim.x + threadIdx.x;
    int stride = gridDim.x * blockDim.x;

    int4* g4 = (int4*)g_grid;
    const int ng4 = GRID_CELLS / 4;
    int4 mone = make_int4(-1, -1, -1, -1);
    for (int i = tid0; i < ng4; i += stride) g4[i] = mone;

    const int nf4 = N_VOX * C_CH / 4;
    float4 z = make_float4(0.f, 0.f, 0.f, 0.f);
    float4* m4 = (float4*)g_mid;
    float4* o4 = (float4*)out;
    for (int i = tid0; i < nf4; i += stride) { m4[i] = z; o4[i] = z; }

    if (blockIdx.x == 0 && threadIdx.x < KV_) g_cnt[threadIdx.x] = 0;
}

// ------------------------------------------------------------------- scatter
// Reference .at[flat].set(arange): last-index-wins = max on duplicates.
__global__ void scatter_kernel(const int* __restrict__ coors) {
    int i = blockIdx.x * blockDim.x + threadIdx.x;
    if (i >= N_VOX) return;
    int4 c = ((const int4*)coors)[i];
    int flat = ((c.x * DD + c.y) * DD + c.z) * DD + c.w;
    atomicMax(&g_grid[flat], i);
}

// -------------------------------------- fused rulebook build + k-compaction
__global__ void build_kernel(const int* __restrict__ coors) {
    int n    = blockIdx.x * blockDim.x + threadIdx.x;
    int lane = threadIdx.x & 31;
    bool live = (n < N_VOX);
    int4 c = ((const int4*)coors)[live ? n : (N_VOX - 1)];
    int base = c.x * DD * DD * DD;

    int k = 0;
    #pragma unroll
    for (int dz = -1; dz <= 1; dz++)
    #pragma unroll
    for (int dy = -1; dy <= 1; dy++)
    #pragma unroll
    for (int dx = -1; dx <= 1; dx++) {
        int nz = c.y + dz, ny = c.z + dy, nx = c.w + dx;
        int idx = -1;
        if (live && (unsigned)nz < DD && (unsigned)ny < DD && (unsigned)nx < DD)
            idx = __ldg(&g_grid[base + (nz * DD + ny) * DD + nx]);
        bool valid = (idx >= 0);
        unsigned mask = __ballot_sync(0xffffffffu, valid);
        if (mask) {
            int leader = __ffs(mask) - 1;
            int wbase = 0;
            if (lane == leader) wbase = atomicAdd(&g_cnt[k], __popc(mask));
            wbase = __shfl_sync(0xffffffffu, wbase, leader);
            if (valid) {
                int p = wbase + __popc(mask & ((1u << lane) - 1u));
                int cap = (k == 13) ? N_VOX : CAP_NC;
                if (p < cap) {
                    int bb = bucket_base(k);
                    g_pin[bb + p]  = idx;
                    g_pout[bb + p] = n;
                }
            }
        }
        k++;
    }
}

// ----------------------------------------------- packed f32x2 helpers
typedef unsigned long long u64t;

__device__ __forceinline__ u64t pack2(float s) {
    u64t r;
    asm("mov.b64 %0, {%1, %1};" : "=l"(r) : "f"(s));
    return r;
}
__device__ __forceinline__ void ffma2(u64t& d, u64t a, u64t b) {
    asm("fma.rn.f32x2 %0, %1, %2, %0;" : "+l"(d) : "l"(a), "l"(b));
}
__device__ __forceinline__ void red_v4(float* ptr, u64t lo, u64t hi) {
    float x, y, z, w;
    asm("mov.b64 {%0, %1}, %2;" : "=f"(x), "=f"(y) : "l"(lo));
    asm("mov.b64 {%0, %1}, %2;" : "=f"(z), "=f"(w) : "l"(hi));
    asm volatile("red.global.add.v4.f32 [%0], {%1, %2, %3, %4};"
                 :: "l"(ptr), "f"(x), "f"(y), "f"(z), "f"(w)
                 : "memory");
}

// --------------------------------------------------- gather-GEMM per (k,chunk)
// Block: 256 thr <-> 128 pairs x 2 half-rows (32 out channels each).
// W[k] staged row-major [c][o] (16KB); 128 feature rows gathered (32KB).
// Per input channel c: thread reads W[c][half*32 .. +31] as 8 LDS.128 that
// are warp-broadcast (even/odd lanes share addresses -> ~1 wavefront each)
// + 16 FFMA2 into 16 u64 accumulators. Feature scalar read once per 4 c.
// Output: 4x red.global.add.v4.f32 into zero-initialized rows.
__global__ __launch_bounds__(256, 3)
void gemm_kernel(const float* __restrict__ fin,
                 const float* __restrict__ Wall,
                 float* __restrict__ fout)
{
    extern __shared__ float sm[];
    float* ws = sm;          // 4096 floats, W[k][c][o]
    float* fs = sm + 4096;   // 8192 floats, gathered features [128][64]

    int bid = blockIdx.x;
    int k, chunk;
    if (bid < CH_CENTER) { k = 13; chunk = bid; }
    else {
        int t = bid - CH_CENTER;
        int j = t >> 7;
        chunk = t & (CH_NC - 1);
        k = (j < 13) ? j : j + 1;
    }
    int mk = g_cnt[k];
    if (k != 13 && mk > CAP_NC) mk = CAP_NC;
    int p0blk = chunk * 128;
    if (p0blk >= mk) return;
    const int rem = min(128, mk - p0blk);
    const int rowbase = bucket_base(k) + p0blk;

    const int tid = threadIdx.x;

    // stage W[k]
    {
        const float4* wsrc = (const float4*)(Wall + k * 4096);
        float4* wdst = (float4*)ws;
        #pragma unroll
        for (int i = 0; i < 4; i++) wdst[tid + i * 256] = wsrc[tid + i * 256];
    }
    // gather feature rows: rem rows x 16 float4
    {
        const float4* fin4 = (const float4*)fin;
        float4* fs4 = (float4*)fs;
        for (int f = tid; f < rem * 16; f += 256)
            fs4[f] = fin4[(size_t)__ldg(&g_pin[rowbase + (f >> 4)]) * 16 + (f & 15)];
    }
    __syncthreads();

    const int pair = min(tid >> 1, rem - 1);
    const int half = tid & 1;

    const float4* fsv = (const float4*)fs;
    u64t acc[16];
    #pragma unroll
    for (int i = 0; i < 16; i++) acc[i] = 0;

    #pragma unroll 2
    for (int c4 = 0; c4 < 16; c4++) {
        float4 f = fsv[pair * 16 + c4];
        #pragma unroll
        for (int j = 0; j < 4; j++) {
            float sc = (j == 0) ? f.x : (j == 1) ? f.y : (j == 2) ? f.z : f.w;
            u64t s = pack2(sc);
            const ulonglong2* wrow =
                (const ulonglong2*)(ws + (c4 * 4 + j) * C_CH + half * 32);
            #pragma unroll
            for (int i = 0; i < 8; i++) {
                ulonglong2 w = wrow[i];
                ffma2(acc[2 * i + 0], s, w.x);
                ffma2(acc[2 * i + 1], s, w.y);
            }
        }
    }

    if ((tid >> 1) < rem) {
        float* dst = fout + (size_t)__ldg(&g_pout[rowbase + pair]) * C_CH + half * 32;
        #pragma unroll
        for (int i = 0; i < 4; i++)
            red_v4(dst + i * 8, acc[4 * i + 0], acc[4 * i + 1]),
            red_v4(dst + i * 8 + 4, acc[4 * i + 2], acc[4 * i + 3]);
    }
}

#define GEMM_SMEM ((4096 + 8192) * 4)

// -------------------------------------------------------------------- launch
extern "C" void kernel_launch(void* const* d_in, const int* in_sizes, int n_in,
                              void* d_out, int out_size)
{
    const float* feats = (const float*)d_in[0];
    const int*   coors = (const int*)d_in[1];
    const float* W0    = (const float*)d_in[2];
    const float* W1    = (const float*)d_in[3];
    float*       out   = (float*)d_out;

    float* mid;
    cudaGetSymbolAddress((void**)&mid, g_mid);

    cudaFuncSetAttribute(gemm_kernel,
                         cudaFuncAttributeMaxDynamicSharedMemorySize, GEMM_SMEM);

    init_kernel<<<2048, 256>>>(out);
    scatter_kernel<<<(N_VOX + 255) / 256, 256>>>(coors);
    build_kernel<<<(N_VOX + 255) / 256, 256>>>(coors);

    gemm_kernel<<<GEMM_BLOCKS, 256, GEMM_SMEM>>>(feats, W0, mid);
    gemm_kernel<<<GEMM_BLOCKS, 256, GEMM_SMEM>>>(mid, W1, out);
}

// round 10
// speedup vs baseline: 2.1256x; 2.1256x over previous
#include <cuda_runtime.h>
#include <cuda_bf16.h>

// Submanifold sparse conv, 2 layers, C=64, KV=27, N=200000, grid 128^3, B=2.
// Per-offset pair buckets -> gather-GEMM on tensor cores via mma.sync
// (m16n8k16 bf16, split hi/lo for fp32-grade accuracy), RED.v2 accumulation.

#define N_VOX   200000
#define C_CH    64
#define KV_     27
#define DD      128
#define BATCH   2
#define GRID_CELLS (BATCH * DD * DD * DD)

#define CAP_NC     16384
#define CH_CENTER  1563                     // ceil(200000/128)
#define CH_NC      128
#define TOT_ROWS   (N_VOX + 26 * CAP_NC)
#define GEMM_BLOCKS (CH_CENTER + 26 * CH_NC)

__device__ int   g_grid[GRID_CELLS];
__device__ int   g_cnt[KV_];
__device__ int   g_pin[TOT_ROWS];
__device__ int   g_pout[TOT_ROWS];
__device__ float g_mid[(size_t)N_VOX * C_CH];

__host__ __device__ __forceinline__ int bucket_base(int k) {
    if (k == 13) return 0;
    int j = (k < 13) ? k : k - 1;
    return N_VOX + j * CAP_NC;
}

// ------------------ init: grid=-1, counters=0, zero mid and out -------------
__global__ void init_kernel(float* __restrict__ out) {
    int tid0 = blockIdx.x * blockDim.x + threadIdx.x;
    int stride = gridDim.x * blockDim.x;

    int4* g4 = (int4*)g_grid;
    const int ng4 = GRID_CELLS / 4;
    int4 mone = make_int4(-1, -1, -1, -1);
    for (int i = tid0; i < ng4; i += stride) g4[i] = mone;

    const int nf4 = N_VOX * C_CH / 4;
    float4 z = make_float4(0.f, 0.f, 0.f, 0.f);
    float4* m4 = (float4*)g_mid;
    float4* o4 = (float4*)out;
    for (int i = tid0; i < nf4; i += stride) { m4[i] = z; o4[i] = z; }

    if (blockIdx.x == 0 && threadIdx.x < KV_) g_cnt[threadIdx.x] = 0;
}

// ------------------------------------------------------------------- scatter
// Reference .at[flat].set(arange): last-index-wins = max on duplicates.
__global__ void scatter_kernel(const int* __restrict__ coors) {
    int i = blockIdx.x * blockDim.x + threadIdx.x;
    if (i >= N_VOX) return;
    int4 c = ((const int4*)coors)[i];
    int flat = ((c.x * DD + c.y) * DD + c.z) * DD + c.w;
    atomicMax(&g_grid[flat], i);
}

// -------------------------------------- fused rulebook build + k-compaction
__global__ void build_kernel(const int* __restrict__ coors) {
    int n    = blockIdx.x * blockDim.x + threadIdx.x;
    int lane = threadIdx.x & 31;
    bool live = (n < N_VOX);
    int4 c = ((const int4*)coors)[live ? n : (N_VOX - 1)];
    int base = c.x * DD * DD * DD;

    int k = 0;
    #pragma unroll
    for (int dz = -1; dz <= 1; dz++)
    #pragma unroll
    for (int dy = -1; dy <= 1; dy++)
    #pragma unroll
    for (int dx = -1; dx <= 1; dx++) {
        int nz = c.y + dz, ny = c.z + dy, nx = c.w + dx;
        int idx = -1;
        if (live && (unsigned)nz < DD && (unsigned)ny < DD && (unsigned)nx < DD)
            idx = __ldg(&g_grid[base + (nz * DD + ny) * DD + nx]);
        bool valid = (idx >= 0);
        unsigned mask = __ballot_sync(0xffffffffu, valid);
        if (mask) {
            int leader = __ffs(mask) - 1;
            int wbase = 0;
            if (lane == leader) wbase = atomicAdd(&g_cnt[k], __popc(mask));
            wbase = __shfl_sync(0xffffffffu, wbase, leader);
            if (valid) {
                int p = wbase + __popc(mask & ((1u << lane) - 1u));
                int cap = (k == 13) ? N_VOX : CAP_NC;
                if (p < cap) {
                    int bb = bucket_base(k);
                    g_pin[bb + p]  = idx;
                    g_pout[bb + p] = n;
                }
            }
        }
        k++;
    }
}

// ======================= mma.sync helpers (portable PTX) ====================
static __device__ __forceinline__ unsigned smem_u32(const void* p) {
    unsigned a;
    asm("{ .reg .u64 t; cvta.to.shared.u64 t, %1; cvt.u32.u64 %0, t; }"
        : "=r"(a) : "l"(p));
    return a;
}

#define LDSM_X4(r0, r1, r2, r3, addr) \
    asm volatile("ldmatrix.sync.aligned.m8n8.x4.shared.b16 {%0,%1,%2,%3}, [%4];" \
        : "=r"(r0), "=r"(r1), "=r"(r2), "=r"(r3) : "r"(addr))

#define LDSM_X4T(r0, r1, r2, r3, addr) \
    asm volatile("ldmatrix.sync.aligned.m8n8.x4.trans.shared.b16 {%0,%1,%2,%3}, [%4];" \
        : "=r"(r0), "=r"(r1), "=r"(r2), "=r"(r3) : "r"(addr))

#define MMA_BF16(d, a0, a1, a2, a3, b0, b1) \
    asm volatile("mma.sync.aligned.m16n8k16.row.col.f32.bf16.bf16.f32 " \
        "{%0,%1,%2,%3}, {%4,%5,%6,%7}, {%8,%9}, {%0,%1,%2,%3};" \
        : "+f"((d)[0]), "+f"((d)[1]), "+f"((d)[2]), "+f"((d)[3]) \
        : "r"(a0), "r"(a1), "r"(a2), "r"(a3), "r"(b0), "r"(b1))

__device__ __forceinline__ void red_v2(float* ptr, float x, float y) {
    asm volatile("red.global.add.v2.f32 [%0], {%1, %2};"
                 :: "l"(ptr), "f"(x), "f"(y) : "memory");
}

// smem layout: padded rows of 72 bf16 (144 B) -> conflict-free ldmatrix
#define APAD 72
#define SM_FH   0                        // A hi: 128 x 72 bf16 = 18432 B
#define SM_FL   (SM_FH + 128 * APAD * 2) // A lo
#define SM_WH   (SM_FL + 128 * APAD * 2) // B hi: 64 x 72 bf16 = 9216 B
#define SM_WL   (SM_WH + 64 * APAD * 2)  // B lo
#define SM_SPO  (SM_WL + 64 * APAD * 2)  // 128 out-row ints
#define SMEM_TOTAL (SM_SPO + 128 * 4)    // 55808 B

// ------------------------------- tensor gather-GEMM per (k, 128-pair chunk)
// A[m][c] (M=128, K=64) = split-bf16 gathered features.
// B[c][o] (K=64, N=64)  = split-bf16 W[k] (natural layout; ldmatrix.trans).
// D = Ah*Bh + Ah*Bl + Al*Bh (fp32 accum; lo*lo ~2^-16 rel, dropped).
// Warp = 16 pairs x 64 out-ch: per k16-step: 2 LDSM.x4 (A) + 8 LDSM.x4 (B)
// + 24 HMMA. Epilogue: red.global.add.v2.f32 into zeroed rows.
__global__ __launch_bounds__(256, 2)
void gemm_kernel(const float* __restrict__ fin,
                 const float* __restrict__ Wall,
                 float* __restrict__ fout)
{
    extern __shared__ char smem[];
    const unsigned sb = smem_u32(smem);
    int* spo = (int*)(smem + SM_SPO);

    int bid = blockIdx.x;
    int k, chunk;
    if (bid < CH_CENTER) { k = 13; chunk = bid; }
    else {
        int t = bid - CH_CENTER;
        int j = t >> 7;
        chunk = t & (CH_NC - 1);
        k = (j < 13) ? j : j + 1;
    }
    int mk = g_cnt[k];
    if (k != 13 && mk > CAP_NC) mk = CAP_NC;
    int p0blk = chunk * 128;
    if (p0blk >= mk) return;
    const int rem = min(128, mk - p0blk);
    const int rowbase = bucket_base(k) + p0blk;

    const int tid  = threadIdx.x;
    const int lane = tid & 31;
    const int warp = tid >> 5;

    // ---- gather features -> split bf16 hi/lo (thread = half row: 32 ch) ----
    {
        const int r = tid >> 1;                    // row 0..127
        const int h = tid & 1;                     // half: ch 0..31 / 32..63
        const int src = __ldg(&g_pin[rowbase + min(r, rem - 1)]);
        const float4* fr = (const float4*)fin + (size_t)src * 16 + h * 8;
        char* dh = smem + SM_FH + r * (APAD * 2) + h * 64;
        char* dl = smem + SM_FL + r * (APAD * 2) + h * 64;
        #pragma unroll
        for (int i = 0; i < 8; i++) {
            float4 v = __ldg(fr + i);
            __nv_bfloat162 h01 = __floats2bfloat162_rn(v.x, v.y);
            __nv_bfloat162 h23 = __floats2bfloat162_rn(v.z, v.w);
            float2 f01 = __bfloat1622float2(h01);
            float2 f23 = __bfloat1622float2(h23);
            __nv_bfloat162 l01 = __floats2bfloat162_rn(v.x - f01.x, v.y - f01.y);
            __nv_bfloat162 l23 = __floats2bfloat162_rn(v.z - f23.x, v.w - f23.y);
            *(uint2*)(dh + i * 8) = make_uint2(*(unsigned*)&h01, *(unsigned*)&h23);
            *(uint2*)(dl + i * 8) = make_uint2(*(unsigned*)&l01, *(unsigned*)&l23);
        }
    }
    // ---- W[k] ([c][o] row-major = [k][n]) -> split bf16 hi/lo ----
    {
        const float* Wk = Wall + k * 4096;
        #pragma unroll
        for (int i = 0; i < 16; i++) {
            int p = tid + i * 256;
            float w = __ldg(&Wk[p]);
            int c = p >> 6, o = p & 63;
            __nv_bfloat16 hh = __float2bfloat16(w);
            __nv_bfloat16 ll = __float2bfloat16(w - __bfloat162float(hh));
            *(__nv_bfloat16*)(smem + SM_WH + (c * APAD + o) * 2) = hh;
            *(__nv_bfloat16*)(smem + SM_WL + (c * APAD + o) * 2) = ll;
        }
    }
    if (tid < 128) spo[tid] = __ldg(&g_pout[rowbase + min(tid, rem - 1)]);
    __syncthreads();

    // ---- mainloop: warp owns pairs [16*warp, 16*warp+16) x all 64 out-ch ----
    float acc[8][4];
    #pragma unroll
    for (int t = 0; t < 8; t++)
        #pragma unroll
        for (int i = 0; i < 4; i++) acc[t][i] = 0.f;

    // A frag address: lanes 0-15 -> rows m0..m15 at col k0; 16-31 -> col k0+8
    const unsigned a_off = (unsigned)((warp * 16 + (lane & 15)) * APAD +
                                      (lane >> 4) * 8) * 2;
    // B frag address (x4.trans): lane groups of 8 ->
    //   g0: rows k0..k0+7 col n0 ; g1: k0+8..k0+15 col n0 ;
    //   g2: k0..k0+7 col n0+8    ; g3: k0+8..k0+15 col n0+8
    const int bg = lane >> 3, bl8 = lane & 7;
    const unsigned b_off = (unsigned)(((bg & 1) * 8 + bl8) * APAD +
                                      (bg >> 1) * 8) * 2;

    #pragma unroll
    for (int ks = 0; ks < 4; ks++) {           // k0 = 16*ks
        const unsigned akk = (unsigned)(16 * ks) * 2;
        unsigned ah0, ah1, ah2, ah3, al0, al1, al2, al3;
        LDSM_X4(ah0, ah1, ah2, ah3, sb + SM_FH + a_off + akk);
        LDSM_X4(al0, al1, al2, al3, sb + SM_FL + a_off + akk);

        const unsigned bkk = (unsigned)(16 * ks) * (APAD * 2);
        #pragma unroll
        for (int t = 0; t < 4; t++) {          // n0 = 16*t -> tiles 2t, 2t+1
            const unsigned bnn = (unsigned)(16 * t) * 2;
            unsigned bh0, bh1, bh2, bh3, bl0, bl1, bl2, bl3;
            LDSM_X4T(bh0, bh1, bh2, bh3, sb + SM_WH + b_off + bkk + bnn);
            MMA_BF16(acc[2 * t],     ah0, ah1, ah2, ah3, bh0, bh1);
            MMA_BF16(acc[2 * t + 1], ah0, ah1, ah2, ah3, bh2, bh3);
            MMA_BF16(acc[2 * t],     al0, al1, al2, al3, bh0, bh1);
            MMA_BF16(acc[2 * t + 1], al0, al1, al2, al3, bh2, bh3);
            LDSM_X4T(bl0, bl1, bl2, bl3, sb + SM_WL + b_off + bkk + bnn);
            MMA_BF16(acc[2 * t],     ah0, ah1, ah2, ah3, bl0, bl1);
            MMA_BF16(acc[2 * t + 1], ah0, ah1, ah2, ah3, bl2, bl3);
        }
    }

    // ---- epilogue: d0,d1 -> row lane>>2 ; d2,d3 -> row +8 ; col 2*(lane&3) ----
    const int r0 = warp * 16 + (lane >> 2);
    const int r1 = r0 + 8;
    const int nc = (lane & 3) * 2;
    const bool ok0 = (r0 < rem), ok1 = (r1 < rem);
    float* d0 = ok0 ? fout + (size_t)spo[r0] * C_CH + nc : 0;
    float* d1 = ok1 ? fout + (size_t)spo[r1] * C_CH + nc : 0;
    #pragma unroll
    for (int t = 0; t < 8; t++) {
        if (ok0) red_v2(d0 + t * 8, acc[t][0], acc[t][1]);
        if (ok1) red_v2(d1 + t * 8, acc[t][2], acc[t][3]);
    }
}

// -------------------------------------------------------------------- launch
extern "C" void kernel_launch(void* const* d_in, const int* in_sizes, int n_in,
                              void* d_out, int out_size)
{
    const float* feats = (const float*)d_in[0];
    const int*   coors = (const int*)d_in[1];
    const float* W0    = (const float*)d_in[2];
    const float* W1    = (const float*)d_in[3];
    float*       out   = (float*)d_out;

    float* mid;
    cudaGetSymbolAddress((void**)&mid, g_mid);

    cudaFuncSetAttribute(gemm_kernel,
                         cudaFuncAttributeMaxDynamicSharedMemorySize, SMEM_TOTAL);

    init_kernel<<<2048, 256>>>(out);
    scatter_kernel<<<(N_VOX + 255) / 256, 256>>>(coors);
    build_kernel<<<(N_VOX + 255) / 256, 256>>>(coors);

    gemm_kernel<<<GEMM_BLOCKS, 256, SMEM_TOTAL>>>(feats, W0, mid);
    gemm_kernel<<<GEMM_BLOCKS, 256, SMEM_TOTAL>>>(mid, W1, out);
}

// round 11
// speedup vs baseline: 2.2264x; 1.0474x over previous
#include <cuda_runtime.h>
#include <cuda_bf16.h>

// Submanifold sparse conv, 2 layers, C=64, KV=27, N=200000, grid 128^3, B=2.
// Self-cleaning state (grid stores idx+1, 0=empty; cleanup kernel resets
// touched cells + counters each launch -> no 16MB grid clear, no init).
// Center offset defines all output rows with st.v2 (no mid/out zeroing);
// other 26 offsets accumulate via red.global.add.v2.f32.
// GEMM: mma.sync m16n8k16 bf16 split hi/lo (3 passes, fp32 accum).

#define N_VOX   200000
#define C_CH    64
#define KV_     27
#define DD      128
#define BATCH   2
#define GRID_CELLS (BATCH * DD * DD * DD)

#define CAP_NC     16384
#define CH_CENTER  1563                     // ceil(200000/128)
#define CH_NC      128
#define TOT_ROWS   (N_VOX + 26 * CAP_NC)
#define REST_BLOCKS (26 * CH_NC)

__device__ int   g_grid[GRID_CELLS];        // idx+1, 0 = empty (self-cleaning)
__device__ int   g_cnt[KV_];                // self-cleaning
__device__ int   g_pin[TOT_ROWS];
__device__ int   g_pout[TOT_ROWS];
__device__ float g_mid[(size_t)N_VOX * C_CH];

__host__ __device__ __forceinline__ int bucket_base(int k) {
    if (k == 13) return 0;
    int j = (k < 13) ? k : k - 1;
    return N_VOX + j * CAP_NC;
}

// ------------------------------------------------------------------- scatter
// Reference .at[flat].set(arange): last-index-wins = max on duplicates.
// Stored as idx+1 so that 0 means empty (grid is zero at launch start).
__global__ void scatter_kernel(const int* __restrict__ coors) {
    int i = blockIdx.x * blockDim.x + threadIdx.x;
    if (i >= N_VOX) return;
    int4 c = ((const int4*)coors)[i];
    int flat = ((c.x * DD + c.y) * DD + c.z) * DD + c.w;
    atomicMax(&g_grid[flat], i + 1);
}

// -------------------------------------- fused rulebook build + k-compaction
__global__ void build_kernel(const int* __restrict__ coors) {
    int n    = blockIdx.x * blockDim.x + threadIdx.x;
    int lane = threadIdx.x & 31;
    bool live = (n < N_VOX);
    int4 c = ((const int4*)coors)[live ? n : (N_VOX - 1)];
    int base = c.x * DD * DD * DD;

    int k = 0;
    #pragma unroll
    for (int dz = -1; dz <= 1; dz++)
    #pragma unroll
    for (int dy = -1; dy <= 1; dy++)
    #pragma unroll
    for (int dx = -1; dx <= 1; dx++) {
        int nz = c.y + dz, ny = c.z + dy, nx = c.w + dx;
        int idx = 0;
        if (live && (unsigned)nz < DD && (unsigned)ny < DD && (unsigned)nx < DD)
            idx = __ldg(&g_grid[base + (nz * DD + ny) * DD + nx]);
        bool valid = (idx > 0);
        unsigned mask = __ballot_sync(0xffffffffu, valid);
        if (mask) {
            int leader = __ffs(mask) - 1;
            int wbase = 0;
            if (lane == leader) wbase = atomicAdd(&g_cnt[k], __popc(mask));
            wbase = __shfl_sync(0xffffffffu, wbase, leader);
            if (valid) {
                int p = wbase + __popc(mask & ((1u << lane) - 1u));
                int cap = (k == 13) ? N_VOX : CAP_NC;
                if (p < cap) {
                    int bb = bucket_base(k);
                    g_pin[bb + p]  = idx - 1;
                    g_pout[bb + p] = n;
                }
            }
        }
        k++;
    }
}

// ------------------------- cleanup: reset touched grid cells + counters ----
__global__ void cleanup_kernel(const int* __restrict__ coors) {
    int i = blockIdx.x * blockDim.x + threadIdx.x;
    if (i < N_VOX) {
        int4 c = ((const int4*)coors)[i];
        g_grid[((c.x * DD + c.y) * DD + c.z) * DD + c.w] = 0;
    }
    if (blockIdx.x == 0 && threadIdx.x < KV_) g_cnt[threadIdx.x] = 0;
}

// ======================= mma.sync helpers (portable PTX) ====================
static __device__ __forceinline__ unsigned smem_u32(const void* p) {
    unsigned a;
    asm("{ .reg .u64 t; cvta.to.shared.u64 t, %1; cvt.u32.u64 %0, t; }"
        : "=r"(a) : "l"(p));
    return a;
}

#define LDSM_X4(r0, r1, r2, r3, addr) \
    asm volatile("ldmatrix.sync.aligned.m8n8.x4.shared.b16 {%0,%1,%2,%3}, [%4];" \
        : "=r"(r0), "=r"(r1), "=r"(r2), "=r"(r3) : "r"(addr))

#define LDSM_X4T(r0, r1, r2, r3, addr) \
    asm volatile("ldmatrix.sync.aligned.m8n8.x4.trans.shared.b16 {%0,%1,%2,%3}, [%4];" \
        : "=r"(r0), "=r"(r1), "=r"(r2), "=r"(r3) : "r"(addr))

#define MMA_BF16(d, a0, a1, a2, a3, b0, b1) \
    asm volatile("mma.sync.aligned.m16n8k16.row.col.f32.bf16.bf16.f32 " \
        "{%0,%1,%2,%3}, {%4,%5,%6,%7}, {%8,%9}, {%0,%1,%2,%3};" \
        : "+f"((d)[0]), "+f"((d)[1]), "+f"((d)[2]), "+f"((d)[3]) \
        : "r"(a0), "r"(a1), "r"(a2), "r"(a3), "r"(b0), "r"(b1))

__device__ __forceinline__ void red_v2(float* ptr, float x, float y) {
    asm volatile("red.global.add.v2.f32 [%0], {%1, %2};"
                 :: "l"(ptr), "f"(x), "f"(y) : "memory");
}
__device__ __forceinline__ void st_v2(float* ptr, float x, float y) {
    asm volatile("st.global.v2.f32 [%0], {%1, %2};"
                 :: "l"(ptr), "f"(x), "f"(y) : "memory");
}

// smem layout: padded rows of 72 bf16 (144 B) -> conflict-free ldmatrix
#define APAD 72
#define SM_FH   0                        // A hi: 128 x 72 bf16 = 18432 B
#define SM_FL   (SM_FH + 128 * APAD * 2) // A lo
#define SM_WH   (SM_FL + 128 * APAD * 2) // B hi: 64 x 72 bf16 = 9216 B
#define SM_WL   (SM_WH + 64 * APAD * 2)  // B lo
#define SM_SPO  (SM_WL + 64 * APAD * 2)  // 128 out-row ints
#define SMEM_TOTAL (SM_SPO + 128 * 4)    // 55808 B

// ------------------------------- tensor gather-GEMM per (k, 128-pair chunk)
// A[m][c] (M=128, K=64) = split-bf16 gathered features.
// B[c][o] (K=64, N=64)  = split-bf16 W[k] (natural layout; ldmatrix.trans).
// D = Ah*Bh + Ah*Bl + Al*Bh (fp32 accum; lo*lo ~2^-16 rel, dropped).
// CENTER: k=13 covers every output row exactly once -> st.v2 defines rows
// (no zeroing anywhere). Rest: red.global.add.v2.f32.
template<bool CENTER>
__global__ __launch_bounds__(256, 2)
void gemm_kernel(const float* __restrict__ fin,
                 const float* __restrict__ Wall,
                 float* __restrict__ fout)
{
    extern __shared__ char smem[];
    const unsigned sb = smem_u32(smem);
    int* spo = (int*)(smem + SM_SPO);

    int k, chunk;
    if (CENTER) { k = 13; chunk = blockIdx.x; }
    else {
        int j = blockIdx.x >> 7;
        chunk = blockIdx.x & (CH_NC - 1);
        k = (j < 13) ? j : j + 1;
    }
    int mk = g_cnt[k];
    if (!CENTER && mk > CAP_NC) mk = CAP_NC;
    int p0blk = chunk * 128;
    if (p0blk >= mk) return;
    const int rem = min(128, mk - p0blk);
    const int rowbase = bucket_base(k) + p0blk;

    const int tid  = threadIdx.x;
    const int lane = tid & 31;
    const int warp = tid >> 5;

    // ---- gather features -> split bf16 hi/lo (thread = half row: 32 ch) ----
    {
        const int r = tid >> 1;                    // row 0..127
        const int h = tid & 1;                     // half: ch 0..31 / 32..63
        const int src = __ldg(&g_pin[rowbase + min(r, rem - 1)]);
        const float4* fr = (const float4*)fin + (size_t)src * 16 + h * 8;
        char* dh = smem + SM_FH + r * (APAD * 2) + h * 64;
        char* dl = smem + SM_FL + r * (APAD * 2) + h * 64;
        #pragma unroll
        for (int i = 0; i < 8; i++) {
            float4 v = __ldg(fr + i);
            __nv_bfloat162 h01 = __floats2bfloat162_rn(v.x, v.y);
            __nv_bfloat162 h23 = __floats2bfloat162_rn(v.z, v.w);
            float2 f01 = __bfloat1622float2(h01);
            float2 f23 = __bfloat1622float2(h23);
            __nv_bfloat162 l01 = __floats2bfloat162_rn(v.x - f01.x, v.y - f01.y);
            __nv_bfloat162 l23 = __floats2bfloat162_rn(v.z - f23.x, v.w - f23.y);
            *(uint2*)(dh + i * 8) = make_uint2(*(unsigned*)&h01, *(unsigned*)&h23);
            *(uint2*)(dl + i * 8) = make_uint2(*(unsigned*)&l01, *(unsigned*)&l23);
        }
    }
    // ---- W[k] ([c][o] row-major) -> split bf16 hi/lo ----
    {
        const float* Wk = Wall + k * 4096;
        #pragma unroll
        for (int i = 0; i < 16; i++) {
            int p = tid + i * 256;
            float w = __ldg(&Wk[p]);
            int c = p >> 6, o = p & 63;
            __nv_bfloat16 hh = __float2bfloat16(w);
            __nv_bfloat16 ll = __float2bfloat16(w - __bfloat162float(hh));
            *(__nv_bfloat16*)(smem + SM_WH + (c * APAD + o) * 2) = hh;
            *(__nv_bfloat16*)(smem + SM_WL + (c * APAD + o) * 2) = ll;
        }
    }
    if (tid < 128) spo[tid] = __ldg(&g_pout[rowbase + min(tid, rem - 1)]);
    __syncthreads();

    // ---- mainloop: warp owns pairs [16*warp, 16*warp+16) x all 64 out-ch ----
    float acc[8][4];
    #pragma unroll
    for (int t = 0; t < 8; t++)
        #pragma unroll
        for (int i = 0; i < 4; i++) acc[t][i] = 0.f;

    const unsigned a_off = (unsigned)((warp * 16 + (lane & 15)) * APAD +
                                      (lane >> 4) * 8) * 2;
    const int bg = lane >> 3, bl8 = lane & 7;
    const unsigned b_off = (unsigned)(((bg & 1) * 8 + bl8) * APAD +
                                      (bg >> 1) * 8) * 2;

    #pragma unroll
    for (int ks = 0; ks < 4; ks++) {           // k0 = 16*ks
        const unsigned akk = (unsigned)(16 * ks) * 2;
        unsigned ah0, ah1, ah2, ah3, al0, al1, al2, al3;
        LDSM_X4(ah0, ah1, ah2, ah3, sb + SM_FH + a_off + akk);
        LDSM_X4(al0, al1, al2, al3, sb + SM_FL + a_off + akk);

        const unsigned bkk = (unsigned)(16 * ks) * (APAD * 2);
        #pragma unroll
        for (int t = 0; t < 4; t++) {          // n0 = 16*t -> tiles 2t, 2t+1
            const unsigned bnn = (unsigned)(16 * t) * 2;
            unsigned bh0, bh1, bh2, bh3, bl0, bl1, bl2, bl3;
            LDSM_X4T(bh0, bh1, bh2, bh3, sb + SM_WH + b_off + bkk + bnn);
            MMA_BF16(acc[2 * t],     ah0, ah1, ah2, ah3, bh0, bh1);
            MMA_BF16(acc[2 * t + 1], ah0, ah1, ah2, ah3, bh2, bh3);
            MMA_BF16(acc[2 * t],     al0, al1, al2, al3, bh0, bh1);
            MMA_BF16(acc[2 * t + 1], al0, al1, al2, al3, bh2, bh3);
            LDSM_X4T(bl0, bl1, bl2, bl3, sb + SM_WL + b_off + bkk + bnn);
            MMA_BF16(acc[2 * t],     ah0, ah1, ah2, ah3, bl0, bl1);
            MMA_BF16(acc[2 * t + 1], ah0, ah1, ah2, ah3, bl2, bl3);
        }
    }

    // ---- epilogue: d0,d1 -> row lane>>2 ; d2,d3 -> row +8 ; col 2*(lane&3) ----
    const int r0 = warp * 16 + (lane >> 2);
    const int r1 = r0 + 8;
    const int nc = (lane & 3) * 2;
    const bool ok0 = (r0 < rem), ok1 = (r1 < rem);
    float* d0 = ok0 ? fout + (size_t)spo[r0] * C_CH + nc : 0;
    float* d1 = ok1 ? fout + (size_t)spo[r1] * C_CH + nc : 0;
    #pragma unroll
    for (int t = 0; t < 8; t++) {
        if (CENTER) {
            if (ok0) st_v2(d0 + t * 8, acc[t][0], acc[t][1]);
            if (ok1) st_v2(d1 + t * 8, acc[t][2], acc[t][3]);
        } else {
            if (ok0) red_v2(d0 + t * 8, acc[t][0], acc[t][1]);
            if (ok1) red_v2(d1 + t * 8, acc[t][2], acc[t][3]);
        }
    }
}

// -------------------------------------------------------------------- launch
extern "C" void kernel_launch(void* const* d_in, const int* in_sizes, int n_in,
                              void* d_out, int out_size)
{
    const float* feats = (const float*)d_in[0];
    const int*   coors = (const int*)d_in[1];
    const float* W0    = (const float*)d_in[2];
    const float* W1    = (const float*)d_in[3];
    float*       out   = (float*)d_out;

    float* mid;
    cudaGetSymbolAddress((void**)&mid, g_mid);

    cudaFuncSetAttribute((const void*)gemm_kernel<true>,
                         cudaFuncAttributeMaxDynamicSharedMemorySize, SMEM_TOTAL);
    cudaFuncSetAttribute((const void*)gemm_kernel<false>,
                         cudaFuncAttributeMaxDynamicSharedMemorySize, SMEM_TOTAL);

    scatter_kernel<<<(N_VOX + 255) / 256, 256>>>(coors);
    build_kernel<<<(N_VOX + 255) / 256, 256>>>(coors);

    // layer 0: center pass defines every row, rest accumulates
    gemm_kernel<true ><<<CH_CENTER,   256, SMEM_TOTAL>>>(feats, W0, mid);
    gemm_kernel<false><<<REST_BLOCKS, 256, SMEM_TOTAL>>>(feats, W0, mid);

    // layer 1
    gemm_kernel<true ><<<CH_CENTER,   256, SMEM_TOTAL>>>(mid, W1, out);
    gemm_kernel<false><<<REST_BLOCKS, 256, SMEM_TOTAL>>>(mid, W1, out);

    // self-clean: reset touched grid cells + bucket counters for next replay
    cleanup_kernel<<<(N_VOX + 255) / 256, 256>>>(coors);
}